// round 9
// baseline (speedup 1.0000x reference)
#include <cuda_runtime.h>
#include <cuda_bf16.h>
#include <cstdint>
#include <cstdio>

// ---------------------------------------------------------------------------
// AtomAttentionPairBias: B=1, Nq=Nk=4096, C=128, H=4, c=32, CZ=16  (all fp32)
//
//   1. init_bias: premultiply lnz*Wbias -> constant bank
//   2. side_kernel<Q/K>: LN -> AdaLN -> {q,gate} / {k,v}; split-tf32 mma
//   3. attn_kernel (WARP-SPECIALIZED): 8 consumer warps do flash attention
//      (tf32 mma QK^T / PV, online softmax); 4 producer warps stream z ONCE
//      and compute the fused LN(z)@Wbias bias for the NEXT tile into a
//      double-buffered Psm. Named-barrier full/empty handshake.
//   4. final_kernel: out = sigmoid(s_q@Ws+bs) * (og@Wo), split-tf32
// ---------------------------------------------------------------------------

#define NSEQ 4096
#define CDIM 128
#define NHEAD 4
#define HDIM 32
#define CZ 16
#define EPS 1e-5f
#define QK_SCALE 0.17677669529663687f   // 1/sqrt(32)

__device__ float g_scratch[6u * NSEQ * CDIM];

// c_bias[0..63]  = lnz[c] * Wbias[c][h]  (row-major [cz][h])
// c_bias[64..67] = per-head column sums of the above
__constant__ float c_bias[CZ * NHEAD + NHEAD];

__device__ __forceinline__ float sigmoidf_(float x) { return 1.f / (1.f + __expf(-x)); }

__device__ __forceinline__ uint32_t f2tf32(float x) {
    uint32_t y; asm("cvt.rna.tf32.f32 %0, %1;" : "=r"(y) : "f"(x)); return y;
}
__device__ __forceinline__ void mma_tf32(float* d, const uint32_t* a, const uint32_t* b) {
    asm volatile("mma.sync.aligned.m16n8k8.row.col.f32.tf32.tf32.f32 "
                 "{%0,%1,%2,%3}, {%4,%5,%6,%7}, {%8,%9}, {%0,%1,%2,%3};"
                 : "+f"(d[0]), "+f"(d[1]), "+f"(d[2]), "+f"(d[3])
                 : "r"(a[0]), "r"(a[1]), "r"(a[2]), "r"(a[3]), "r"(b[0]), "r"(b[1]));
}
__device__ __forceinline__ void cp16(float* dst, const float* src) {
    uint32_t d = (uint32_t)__cvta_generic_to_shared(dst);
    asm volatile("cp.async.cg.shared.global [%0], [%1], 16;" :: "r"(d), "l"(src));
}

// ------------------------------ init_bias ----------------------------------
__global__ void init_bias(const float* __restrict__ lnz, const float* __restrict__ wb,
                          float* __restrict__ out) {
    int t = threadIdx.x;
    if (t < 64) out[t] = lnz[t >> 2] * wb[t];
    if (t >= 64 && t < 68) {
        int h = t - 64;
        float s = 0.f;
        for (int c = 0; c < CZ; c++) s += lnz[c] * wb[c * 4 + h];
        out[t] = s;
    }
}

// ------------------- split-tf32 dual GEMM tile helper -----------------------
#define SA_STRIDE 132
#define SW_STRIDE 136

template<bool SAME_A>
__device__ __forceinline__ void gemm_dual(
    const float* __restrict__ sA1, const float* __restrict__ sA2,
    const float* __restrict__ gW1, const float* __restrict__ gW2,
    float* sW, int tid, float acc1[4][4], float acc2[4][4]) {

    const int lane = tid & 31, warp = tid >> 5;
    const int gid = lane >> 2, ctg = lane & 3;
    const int r0 = (warp & 1) * 16;
    const int c0 = (warp >> 1) * 32;

    #pragma unroll
    for (int nt = 0; nt < 4; nt++)
        #pragma unroll
        for (int j = 0; j < 4; j++) { acc1[nt][j] = 0.f; acc2[nt][j] = 0.f; }

    for (int kc = 0; kc < CDIM; kc += 64) {
        __syncthreads();   // protect sW from previous chunk's readers
        #pragma unroll
        for (int i = 0; i < 8; i++) {
            int e = tid + i * 256;
            int r = e >> 5, c4 = e & 31;
            cp16(sW + r * SW_STRIDE + c4 * 4, gW1 + (size_t)(kc + r) * CDIM + c4 * 4);
            cp16(sW + 64 * SW_STRIDE + r * SW_STRIDE + c4 * 4,
                 gW2 + (size_t)(kc + r) * CDIM + c4 * 4);
        }
        asm volatile("cp.async.commit_group;\ncp.async.wait_group 0;" ::: "memory");
        __syncthreads();

        #pragma unroll
        for (int ks = 0; ks < 8; ks++) {
            int kg = kc + ks * 8;
            uint32_t a1h[4], a1l[4], a2h[4], a2l[4];
            {
                const float* ap = sA1 + (r0 + gid) * SA_STRIDE + kg + ctg;
                float x;
                x = ap[0];               a1h[0] = f2tf32(x); a1l[0] = f2tf32(x - __uint_as_float(a1h[0]));
                x = ap[8 * SA_STRIDE];   a1h[1] = f2tf32(x); a1l[1] = f2tf32(x - __uint_as_float(a1h[1]));
                x = ap[4];               a1h[2] = f2tf32(x); a1l[2] = f2tf32(x - __uint_as_float(a1h[2]));
                x = ap[8 * SA_STRIDE+4]; a1h[3] = f2tf32(x); a1l[3] = f2tf32(x - __uint_as_float(a1h[3]));
            }
            if (!SAME_A) {
                const float* ap = sA2 + (r0 + gid) * SA_STRIDE + kg + ctg;
                float x;
                x = ap[0];               a2h[0] = f2tf32(x); a2l[0] = f2tf32(x - __uint_as_float(a2h[0]));
                x = ap[8 * SA_STRIDE];   a2h[1] = f2tf32(x); a2l[1] = f2tf32(x - __uint_as_float(a2h[1]));
                x = ap[4];               a2h[2] = f2tf32(x); a2l[2] = f2tf32(x - __uint_as_float(a2h[2]));
                x = ap[8 * SA_STRIDE+4]; a2h[3] = f2tf32(x); a2l[3] = f2tf32(x - __uint_as_float(a2h[3]));
            }
            #pragma unroll
            for (int nt = 0; nt < 4; nt++) {
                const float* bp = sW + (ks * 8 + ctg) * SW_STRIDE + c0 + nt * 8 + gid;
                uint32_t bh[2], bl[2];
                float b0 = bp[0], b1 = bp[4 * SW_STRIDE];
                bh[0] = f2tf32(b0); bl[0] = f2tf32(b0 - __uint_as_float(bh[0]));
                bh[1] = f2tf32(b1); bl[1] = f2tf32(b1 - __uint_as_float(bh[1]));
                mma_tf32(acc1[nt], a1h, bh);
                mma_tf32(acc1[nt], a1h, bl);
                mma_tf32(acc1[nt], a1l, bh);
                const float* bp2 = bp + 64 * SW_STRIDE;
                b0 = bp2[0]; b1 = bp2[4 * SW_STRIDE];
                bh[0] = f2tf32(b0); bl[0] = f2tf32(b0 - __uint_as_float(bh[0]));
                bh[1] = f2tf32(b1); bl[1] = f2tf32(b1 - __uint_as_float(bh[1]));
                if (SAME_A) {
                    mma_tf32(acc2[nt], a1h, bh);
                    mma_tf32(acc2[nt], a1h, bl);
                    mma_tf32(acc2[nt], a1l, bh);
                } else {
                    mma_tf32(acc2[nt], a2h, bh);
                    mma_tf32(acc2[nt], a2h, bl);
                    mma_tf32(acc2[nt], a2l, bh);
                }
            }
        }
    }
}

#define SMEM_SIDE_FLOATS (2 * 32 * SA_STRIDE + 2 * 64 * SW_STRIDE)
#define SMEM_SIDE_BYTES  (SMEM_SIDE_FLOATS * 4)

// ------------------------------ side kernel --------------------------------
template<int SIDE>
__global__ __launch_bounds__(256) void side_kernel(
    const float* __restrict__ ga, const float* __restrict__ gs,
    const float* __restrict__ sscale,
    const float* __restrict__ Wg, const float* __restrict__ bg,
    const float* __restrict__ Wb,
    const float* __restrict__ W1, const float* __restrict__ b1,
    const float* __restrict__ W2,
    float* __restrict__ out1, float* __restrict__ out2) {

    extern __shared__ float smem[];
    float* sA = smem;
    float* sS = smem + 32 * SA_STRIDE;
    float* sW = smem + 2 * 32 * SA_STRIDE;

    const int tid = threadIdx.x;
    const int lane = tid & 31, warp = tid >> 5;
    const int gid = lane >> 2, ctg = lane & 3;
    const int r0 = (warp & 1) * 16;
    const int c0 = (warp >> 1) * 32;
    const int row0 = blockIdx.x * 32;

    {
        float4 sc = ((const float4*)sscale)[lane];
        #pragma unroll
        for (int rr = 0; rr < 4; rr++) {
            int lrow = rr * 8 + warp;
            const float4* ap = (const float4*)(ga + (size_t)(row0 + lrow) * CDIM);
            const float4* sp = (const float4*)(gs + (size_t)(row0 + lrow) * CDIM);
            float4 av = ap[lane];
            float4 sv = sp[lane];
            float s1 = av.x + av.y + av.z + av.w;
            float s2 = av.x*av.x + av.y*av.y + av.z*av.z + av.w*av.w;
            float t1 = sv.x + sv.y + sv.z + sv.w;
            float t2 = sv.x*sv.x + sv.y*sv.y + sv.z*sv.z + sv.w*sv.w;
            #pragma unroll
            for (int o = 16; o > 0; o >>= 1) {
                s1 += __shfl_xor_sync(~0u, s1, o);
                s2 += __shfl_xor_sync(~0u, s2, o);
                t1 += __shfl_xor_sync(~0u, t1, o);
                t2 += __shfl_xor_sync(~0u, t2, o);
            }
            float ma = s1 * (1.f/CDIM);
            float ra = rsqrtf(s2 * (1.f/CDIM) - ma*ma + EPS);
            float ms = t1 * (1.f/CDIM);
            float rs = rsqrtf(t2 * (1.f/CDIM) - ms*ms + EPS);
            float* pa = sA + lrow * SA_STRIDE + lane * 4;
            float* ps = sS + lrow * SA_STRIDE + lane * 4;
            pa[0] = (av.x - ma) * ra; pa[1] = (av.y - ma) * ra;
            pa[2] = (av.z - ma) * ra; pa[3] = (av.w - ma) * ra;
            ps[0] = (sv.x - ms) * rs * sc.x; ps[1] = (sv.y - ms) * rs * sc.y;
            ps[2] = (sv.z - ms) * rs * sc.z; ps[3] = (sv.w - ms) * rs * sc.w;
        }
    }
    __syncthreads();

    float accG[4][4], accB[4][4];
    gemm_dual<true>(sS, sS, Wg, Wb, sW, tid, accG, accB);

    __syncthreads();
    #pragma unroll
    for (int nt = 0; nt < 4; nt++) {
        int col = c0 + nt * 8 + 2 * ctg;
        float bg0 = bg[col], bg1 = bg[col + 1];
        #pragma unroll
        for (int i = 0; i < 2; i++) {
            int lrow = r0 + gid + i * 8;
            float* pr = sS + lrow * SA_STRIDE + col;
            const float* pl = sA + lrow * SA_STRIDE + col;
            pr[0] = sigmoidf_(accG[nt][2*i]   + bg0) * pl[0] + accB[nt][2*i];
            pr[1] = sigmoidf_(accG[nt][2*i+1] + bg1) * pl[1] + accB[nt][2*i+1];
        }
    }

    float acc1[4][4], acc2[4][4];
    gemm_dual<true>(sS, sS, W1, W2, sW, tid, acc1, acc2);

    #pragma unroll
    for (int nt = 0; nt < 4; nt++) {
        int col = c0 + nt * 8 + 2 * ctg;
        float bb0 = 0.f, bb1 = 0.f;
        if (SIDE == 0) { bb0 = b1[col]; bb1 = b1[col + 1]; }
        #pragma unroll
        for (int i = 0; i < 2; i++) {
            int grow = row0 + r0 + gid + i * 8;
            size_t idx = (size_t)grow * CDIM + col;
            if (SIDE == 0) {
                out1[idx]     = (acc1[nt][2*i]   + bb0) * QK_SCALE;
                out1[idx + 1] = (acc1[nt][2*i+1] + bb1) * QK_SCALE;
                out2[idx]     = sigmoidf_(acc2[nt][2*i]);
                out2[idx + 1] = sigmoidf_(acc2[nt][2*i+1]);
            } else {
                out1[idx]     = acc1[nt][2*i];
                out1[idx + 1] = acc1[nt][2*i+1];
                out2[idx]     = acc2[nt][2*i];
                out2[idx + 1] = acc2[nt][2*i+1];
            }
        }
    }
}

// ------------------------------ final kernel -------------------------------
__global__ __launch_bounds__(256) void final_kernel(
    const float* __restrict__ og, const float* __restrict__ sq,
    const float* __restrict__ Wo, const float* __restrict__ Ws,
    const float* __restrict__ bs, float* __restrict__ out) {

    extern __shared__ float smem[];
    float* sA1 = smem;
    float* sA2 = smem + 32 * SA_STRIDE;
    float* sW  = smem + 2 * 32 * SA_STRIDE;

    const int tid = threadIdx.x;
    const int lane = tid & 31, warp = tid >> 5;
    const int gid = lane >> 2, ctg = lane & 3;
    const int r0 = (warp & 1) * 16;
    const int c0 = (warp >> 1) * 32;
    const int row0 = blockIdx.x * 32;

    #pragma unroll
    for (int i = 0; i < 4; i++) {
        int e = tid + i * 256;
        int r = e >> 5, c4 = e & 31;
        cp16(sA1 + r * SA_STRIDE + c4 * 4, og + (size_t)(row0 + r) * CDIM + c4 * 4);
        cp16(sA2 + r * SA_STRIDE + c4 * 4, sq + (size_t)(row0 + r) * CDIM + c4 * 4);
    }
    asm volatile("cp.async.commit_group;\ncp.async.wait_group 0;" ::: "memory");

    float acc1[4][4], acc2[4][4];
    gemm_dual<false>(sA1, sA2, Wo, Ws, sW, tid, acc1, acc2);

    #pragma unroll
    for (int nt = 0; nt < 4; nt++) {
        int col = c0 + nt * 8 + 2 * ctg;
        float b0 = bs[col], b1 = bs[col + 1];
        #pragma unroll
        for (int i = 0; i < 2; i++) {
            int grow = row0 + r0 + gid + i * 8;
            size_t idx = (size_t)grow * CDIM + col;
            out[idx]     = sigmoidf_(acc2[nt][2*i]   + b0) * acc1[nt][2*i];
            out[idx + 1] = sigmoidf_(acc2[nt][2*i+1] + b1) * acc1[nt][2*i+1];
        }
    }
}

// --------------------------- attention kernel ------------------------------
// 384 threads: warps 0-7 consumers (flash attention), warps 8-11 producers
// (z-bias for next tile into double-buffered Psm).
// Named barriers: 1,2 = full[0,1] (count 384); 3,4 = empty[0,1] (count 384);
//                 5 = consumer-only K/V reuse guard (count 256).
#define K_STRIDE 132
#define V_STRIDE 136
#define P_STRIDE 68
#define PBUF (NHEAD * 32 * P_STRIDE)
#define SMEM_FLOATS (64 * K_STRIDE + 64 * V_STRIDE + 2 * PBUF)
#define SMEM_BYTES  (SMEM_FLOATS * 4)
#define NTILES (NSEQ / 64)

__global__ __launch_bounds__(384, 1) void attn_kernel(
    const float* __restrict__ z,
    const float* __restrict__ gq, const float* __restrict__ gk,
    const float* __restrict__ gv, const float* __restrict__ gg,
    float* __restrict__ og) {

    extern __shared__ float smem[];
    float* Ksm = smem;
    float* Vsm = smem + 64 * K_STRIDE;
    float* Psm = Vsm + 64 * V_STRIDE;

    const int tid = threadIdx.x;
    const int qg0 = blockIdx.x * 32;

    if (tid >= 256) {
        // ======================= PRODUCER warps =======================
        const int ptid = tid - 256;
        const int kk0 = ptid & 63;           // key column within tile
        const int qq0 = ptid >> 6;           // 0 or 1; q = qq0 + 2*qi
        const float csum0 = c_bias[64], csum1 = c_bias[65];
        const float csum2 = c_bias[66], csum3 = c_bias[67];

        // 2-deep rolling z prefetch across the whole tile sequence
        float4 zb[2][4];
        #pragma unroll
        for (int u = 0; u < 2; u++) {
            const float4* zp = (const float4*)(z + ((size_t)(qg0 + qq0 + u * 2) * NSEQ + kk0) * CZ);
            zb[u][0] = zp[0]; zb[u][1] = zp[1]; zb[u][2] = zp[2]; zb[u][3] = zp[3];
        }

        for (int t = 0; t < NTILES; t++) {
            float* Pbuf = Psm + (t & 1) * PBUF;
            if (t >= 2)
                asm volatile("bar.sync %0, 384;" :: "r"(3 + (t & 1)) : "memory");
            const int kb = t * 64;
            #pragma unroll 4
            for (int qi = 0; qi < 16; qi++) {
                const int pb2 = qi & 1;      // t*16 even -> (u&1) == (qi&1)
                float4 zc[4] = { zb[pb2][0], zb[pb2][1], zb[pb2][2], zb[pb2][3] };
                // prefetch u+2
                {
                    int qin = (qi + 2) & 15;
                    int kbn = kb + (((qi + 2) >> 4) << 6);
                    if (kbn >= NSEQ) kbn = 0;   // tail: harmless valid reload
                    const float4* zn = (const float4*)(z + ((size_t)(qg0 + qq0 + qin * 2) * NSEQ + kbn + kk0) * CZ);
                    zb[pb2][0] = zn[0]; zb[pb2][1] = zn[1];
                    zb[pb2][2] = zn[2]; zb[pb2][3] = zn[3];
                }
                float s1 = 0.f, s2 = 0.f, d0 = 0.f, d1 = 0.f, d2 = 0.f, d3 = 0.f;
                #pragma unroll
                for (int j = 0; j < 4; j++) {
                    float4 v = zc[j];
                    int cb = j * 4;
                    s1 += v.x + v.y + v.z + v.w;
                    s2 += v.x*v.x + v.y*v.y + v.z*v.z + v.w*v.w;
                    d0 += v.x*c_bias[(cb+0)*4+0]; d1 += v.x*c_bias[(cb+0)*4+1];
                    d2 += v.x*c_bias[(cb+0)*4+2]; d3 += v.x*c_bias[(cb+0)*4+3];
                    d0 += v.y*c_bias[(cb+1)*4+0]; d1 += v.y*c_bias[(cb+1)*4+1];
                    d2 += v.y*c_bias[(cb+1)*4+2]; d3 += v.y*c_bias[(cb+1)*4+3];
                    d0 += v.z*c_bias[(cb+2)*4+0]; d1 += v.z*c_bias[(cb+2)*4+1];
                    d2 += v.z*c_bias[(cb+2)*4+2]; d3 += v.z*c_bias[(cb+2)*4+3];
                    d0 += v.w*c_bias[(cb+3)*4+0]; d1 += v.w*c_bias[(cb+3)*4+1];
                    d2 += v.w*c_bias[(cb+3)*4+2]; d3 += v.w*c_bias[(cb+3)*4+3];
                }
                float mm = s1 * (1.f/CZ);
                float rstd = rsqrtf(s2 * (1.f/CZ) - mm * mm + EPS);
                int q = qq0 + qi * 2;
                float* pb = Pbuf + q * P_STRIDE + kk0;
                pb[0 * 32 * P_STRIDE] = (d0 - mm * csum0) * rstd;
                pb[1 * 32 * P_STRIDE] = (d1 - mm * csum1) * rstd;
                pb[2 * 32 * P_STRIDE] = (d2 - mm * csum2) * rstd;
                pb[3 * 32 * P_STRIDE] = (d3 - mm * csum3) * rstd;
            }
            asm volatile("bar.arrive %0, 384;" :: "r"(1 + (t & 1)) : "memory");
        }
        return;
    }

    // ======================= CONSUMER warps =======================
    const int lane = tid & 31, warp = tid >> 5;
    const int h = warp >> 1, qh = warp & 1;
    const int gid = lane >> 2, ctg = lane & 3;

    // Q fragments (A of m16n8k8 tf32), q pre-scaled by 1/sqrt(c)
    uint32_t qa[4][4];
    {
        int r0 = qg0 + qh * 16 + gid;
        const float* qp = gq + (size_t)r0 * CDIM + h * HDIM + ctg;
        #pragma unroll
        for (int ks = 0; ks < 4; ks++) {
            qa[ks][0] = f2tf32(qp[ks*8]);
            qa[ks][1] = f2tf32(qp[8*CDIM + ks*8]);
            qa[ks][2] = f2tf32(qp[ks*8 + 4]);
            qa[ks][3] = f2tf32(qp[8*CDIM + ks*8 + 4]);
        }
    }

    float O[4][4];
    #pragma unroll
    for (int i = 0; i < 4; i++) { O[i][0]=O[i][1]=O[i][2]=O[i][3]=0.f; }
    float m1 = -1e30f, m2 = -1e30f, l1 = 0.f, l2 = 0.f;

    for (int t = 0; t < NTILES; t++) {
        const int kb = t * 64;
        // all consumers done reading previous K/V tile
        asm volatile("bar.sync 5, 256;" ::: "memory");

        // prefetch K/V tile (256 consumer threads)
        #pragma unroll
        for (int i = 0; i < 8; i++) {
            int e = tid + i * 256;
            int r = e >> 5, c4 = e & 31;
            cp16(Ksm + r * K_STRIDE + c4 * 4, gk + (size_t)(kb + r) * CDIM + c4 * 4);
        }
        #pragma unroll
        for (int i = 0; i < 8; i++) {
            int e = tid + i * 256;
            int r = e >> 5, c4 = e & 31;
            cp16(Vsm + r * V_STRIDE + c4 * 4, gv + (size_t)(kb + r) * CDIM + c4 * 4);
        }
        asm volatile("cp.async.commit_group;\ncp.async.wait_group 0;" ::: "memory");

        // wait for producers' bias tile (also rendezvous: everyone's cp.async done)
        asm volatile("bar.sync %0, 384;" :: "r"(1 + (t & 1)) : "memory");
        float* Pbuf = Psm + (t & 1) * PBUF;

        // ---- QK^T (tf32 mma): S[16q x 64k] per warp
        float S[8][4];
        #pragma unroll
        for (int nt = 0; nt < 8; nt++) {
            S[nt][0] = S[nt][1] = S[nt][2] = S[nt][3] = 0.f;
            const float* kp = Ksm + (nt * 8 + gid) * K_STRIDE + h * HDIM + ctg;
            #pragma unroll
            for (int ks = 0; ks < 4; ks++) {
                uint32_t b[2];
                b[0] = __float_as_uint(kp[ks * 8]);
                b[1] = __float_as_uint(kp[ks * 8 + 4]);
                mma_tf32(S[nt], qa[ks], b);
            }
        }

        // ---- bias add + online softmax
        float* pwarp = Pbuf + h * 32 * P_STRIDE + (qh * 16) * P_STRIDE;
        float mx1 = -1e30f, mx2 = -1e30f;
        #pragma unroll
        for (int nt = 0; nt < 8; nt++) {
            int col = nt * 8 + 2 * ctg;
            S[nt][0] += pwarp[gid * P_STRIDE + col];
            S[nt][1] += pwarp[gid * P_STRIDE + col + 1];
            S[nt][2] += pwarp[(gid + 8) * P_STRIDE + col];
            S[nt][3] += pwarp[(gid + 8) * P_STRIDE + col + 1];
            mx1 = fmaxf(mx1, fmaxf(S[nt][0], S[nt][1]));
            mx2 = fmaxf(mx2, fmaxf(S[nt][2], S[nt][3]));
        }
        mx1 = fmaxf(mx1, __shfl_xor_sync(~0u, mx1, 1));
        mx1 = fmaxf(mx1, __shfl_xor_sync(~0u, mx1, 2));
        mx2 = fmaxf(mx2, __shfl_xor_sync(~0u, mx2, 1));
        mx2 = fmaxf(mx2, __shfl_xor_sync(~0u, mx2, 2));
        float mn1 = fmaxf(m1, mx1), mn2 = fmaxf(m2, mx2);
        float al1 = __expf(m1 - mn1), al2 = __expf(m2 - mn2);
        float rs1 = 0.f, rs2 = 0.f;
        #pragma unroll
        for (int nt = 0; nt < 8; nt++) {
            float p0 = __expf(S[nt][0] - mn1);
            float p1 = __expf(S[nt][1] - mn1);
            float p2 = __expf(S[nt][2] - mn2);
            float p3 = __expf(S[nt][3] - mn2);
            rs1 += p0 + p1; rs2 += p2 + p3;
            int col = nt * 8 + 2 * ctg;
            pwarp[gid * P_STRIDE + col]           = __uint_as_float(f2tf32(p0));
            pwarp[gid * P_STRIDE + col + 1]       = __uint_as_float(f2tf32(p1));
            pwarp[(gid + 8) * P_STRIDE + col]     = __uint_as_float(f2tf32(p2));
            pwarp[(gid + 8) * P_STRIDE + col + 1] = __uint_as_float(f2tf32(p3));
        }
        rs1 += __shfl_xor_sync(~0u, rs1, 1); rs1 += __shfl_xor_sync(~0u, rs1, 2);
        rs2 += __shfl_xor_sync(~0u, rs2, 1); rs2 += __shfl_xor_sync(~0u, rs2, 2);
        l1 = l1 * al1 + rs1; l2 = l2 * al2 + rs2;
        m1 = mn1; m2 = mn2;
        #pragma unroll
        for (int on = 0; on < 4; on++) {
            O[on][0] *= al1; O[on][1] *= al1; O[on][2] *= al2; O[on][3] *= al2;
        }
        __syncwarp();

        // ---- PV (tf32 mma): O[16q x 32c] += P[16q x 64k] @ V[64k x 32c]
        #pragma unroll
        for (int on = 0; on < 4; on++) {
            #pragma unroll
            for (int ks = 0; ks < 8; ks++) {
                uint32_t a[4], b[2];
                const float* pp = pwarp + gid * P_STRIDE + ks * 8 + ctg;
                a[0] = __float_as_uint(pp[0]);
                a[1] = __float_as_uint(pp[8 * P_STRIDE]);
                a[2] = __float_as_uint(pp[4]);
                a[3] = __float_as_uint(pp[8 * P_STRIDE + 4]);
                const float* vp = Vsm + (ks * 8 + ctg) * V_STRIDE + h * HDIM + on * 8 + gid;
                b[0] = __float_as_uint(vp[0]);
                b[1] = __float_as_uint(vp[4 * V_STRIDE]);
                mma_tf32(O[on], a, b);
            }
        }
        // release Psm buffer to producers
        asm volatile("bar.arrive %0, 384;" :: "r"(3 + (t & 1)) : "memory");
    }

    // ---- epilogue: normalize, gate, store
    float r1 = 1.f / l1, r2 = 1.f / l2;
    int row1 = qg0 + qh * 16 + gid, row2 = row1 + 8;
    #pragma unroll
    for (int on = 0; on < 4; on++) {
        int col = h * HDIM + on * 8 + 2 * ctg;
        size_t i1 = (size_t)row1 * CDIM + col;
        size_t i2 = (size_t)row2 * CDIM + col;
        og[i1]     = O[on][0] * r1 * gg[i1];
        og[i1 + 1] = O[on][1] * r1 * gg[i1 + 1];
        og[i2]     = O[on][2] * r2 * gg[i2];
        og[i2 + 1] = O[on][3] * r2 * gg[i2 + 1];
    }
}

// ------------------------------ launch -------------------------------------
extern "C" void kernel_launch(void* const* d_in, const int* in_sizes, int n_in,
                              void* d_out, int out_size) {
    const float* a_q      = (const float*)d_in[0];
    const float* a_k      = (const float*)d_in[1];
    const float* z        = (const float*)d_in[2];
    const float* s_q      = (const float*)d_in[3];
    const float* s_k      = (const float*)d_in[4];
    const float* Wg_q     = (const float*)d_in[5];
    const float* bg_q     = (const float*)d_in[6];
    const float* Wb_q     = (const float*)d_in[7];
    const float* sscale_q = (const float*)d_in[8];
    const float* Wg_k     = (const float*)d_in[9];
    const float* bg_k     = (const float*)d_in[10];
    const float* Wb_k     = (const float*)d_in[11];
    const float* sscale_k = (const float*)d_in[12];
    const float* lnz      = (const float*)d_in[13];
    const float* Wq       = (const float*)d_in[14];
    const float* bq       = (const float*)d_in[15];
    const float* Wk       = (const float*)d_in[16];
    const float* Wv       = (const float*)d_in[17];
    const float* Wbias    = (const float*)d_in[18];
    const float* Wgate    = (const float*)d_in[19];
    const float* Wo       = (const float*)d_in[20];
    const float* Ws       = (const float*)d_in[21];
    const float* bs       = (const float*)d_in[22];

    float* scratch = nullptr;
    cudaGetSymbolAddress((void**)&scratch, g_scratch);
    const size_t SL = (size_t)NSEQ * CDIM;
    float* qbuf  = scratch + 0 * SL;
    float* gbuf  = scratch + 1 * SL;
    float* kbuf  = scratch + 2 * SL;
    float* vbuf  = scratch + 3 * SL;
    float* ogbuf = scratch + 4 * SL;
    float* biasw = scratch + 5 * SL;

    init_bias<<<1, 96>>>(lnz, Wbias, biasw);
    cudaMemcpyToSymbolAsync(c_bias, biasw, (CZ * NHEAD + NHEAD) * sizeof(float), 0,
                            cudaMemcpyDeviceToDevice, 0);

    cudaFuncSetAttribute(side_kernel<0>, cudaFuncAttributeMaxDynamicSharedMemorySize,
                         SMEM_SIDE_BYTES);
    cudaFuncSetAttribute(side_kernel<1>, cudaFuncAttributeMaxDynamicSharedMemorySize,
                         SMEM_SIDE_BYTES);
    cudaFuncSetAttribute(final_kernel, cudaFuncAttributeMaxDynamicSharedMemorySize,
                         SMEM_SIDE_BYTES);
    cudaFuncSetAttribute(attn_kernel, cudaFuncAttributeMaxDynamicSharedMemorySize,
                         SMEM_BYTES);

    side_kernel<0><<<NSEQ / 32, 256, SMEM_SIDE_BYTES>>>(
        a_q, s_q, sscale_q, Wg_q, bg_q, Wb_q, Wq, bq, Wgate, qbuf, gbuf);
    side_kernel<1><<<NSEQ / 32, 256, SMEM_SIDE_BYTES>>>(
        a_k, s_k, sscale_k, Wg_k, bg_k, Wb_k, Wk, nullptr, Wv, kbuf, vbuf);

    attn_kernel<<<NSEQ / 32, 384, SMEM_BYTES>>>(z, qbuf, kbuf, vbuf, gbuf, ogbuf);

    final_kernel<<<NSEQ / 32, 256, SMEM_SIDE_BYTES>>>(
        ogbuf, s_q, Wo, Ws, bs, (float*)d_out);
}

// round 10
// speedup vs baseline: 1.0025x; 1.0025x over previous
#include <cuda_runtime.h>
#include <cuda_bf16.h>
#include <cstdint>
#include <cstdio>

// ---------------------------------------------------------------------------
// AtomAttentionPairBias: B=1, Nq=Nk=4096, C=128, H=4, c=32, CZ=16  (all fp32)
//
//   1. init_bias: premultiply lnz*Wbias -> constant bank
//   2. side_kernel<Q/K>: LN -> AdaLN -> {q,gate} / {k,v}; split-tf32 mma
//   3. attn_kernel (WARP-SPECIALIZED): 8 consumer warps do flash attention
//      (tf32 mma QK^T / PV, online softmax); 4 producer warps stream z ONCE
//      and compute the fused LN(z)@Wbias bias for the NEXT tile into a
//      double-buffered Psm. Named-barrier full/empty handshake.
//   4. final_kernel: out = sigmoid(s_q@Ws+bs) * (og@Wo), split-tf32
// ---------------------------------------------------------------------------

#define NSEQ 4096
#define CDIM 128
#define NHEAD 4
#define HDIM 32
#define CZ 16
#define EPS 1e-5f
#define QK_SCALE 0.17677669529663687f   // 1/sqrt(32)

__device__ float g_scratch[6u * NSEQ * CDIM];

// c_bias[0..63]  = lnz[c] * Wbias[c][h]  (row-major [cz][h])
// c_bias[64..67] = per-head column sums of the above
__constant__ float c_bias[CZ * NHEAD + NHEAD];

__device__ __forceinline__ float sigmoidf_(float x) { return 1.f / (1.f + __expf(-x)); }

__device__ __forceinline__ uint32_t f2tf32(float x) {
    uint32_t y; asm("cvt.rna.tf32.f32 %0, %1;" : "=r"(y) : "f"(x)); return y;
}
__device__ __forceinline__ void mma_tf32(float* d, const uint32_t* a, const uint32_t* b) {
    asm volatile("mma.sync.aligned.m16n8k8.row.col.f32.tf32.tf32.f32 "
                 "{%0,%1,%2,%3}, {%4,%5,%6,%7}, {%8,%9}, {%0,%1,%2,%3};"
                 : "+f"(d[0]), "+f"(d[1]), "+f"(d[2]), "+f"(d[3])
                 : "r"(a[0]), "r"(a[1]), "r"(a[2]), "r"(a[3]), "r"(b[0]), "r"(b[1]));
}
__device__ __forceinline__ void cp16(float* dst, const float* src) {
    uint32_t d = (uint32_t)__cvta_generic_to_shared(dst);
    asm volatile("cp.async.cg.shared.global [%0], [%1], 16;" :: "r"(d), "l"(src));
}

// ------------------------------ init_bias ----------------------------------
__global__ void init_bias(const float* __restrict__ lnz, const float* __restrict__ wb,
                          float* __restrict__ out) {
    int t = threadIdx.x;
    if (t < 64) out[t] = lnz[t >> 2] * wb[t];
    if (t >= 64 && t < 68) {
        int h = t - 64;
        float s = 0.f;
        for (int c = 0; c < CZ; c++) s += lnz[c] * wb[c * 4 + h];
        out[t] = s;
    }
}

// ------------------- split-tf32 dual GEMM tile helper -----------------------
#define SA_STRIDE 132
#define SW_STRIDE 136

template<bool SAME_A>
__device__ __forceinline__ void gemm_dual(
    const float* __restrict__ sA1, const float* __restrict__ sA2,
    const float* __restrict__ gW1, const float* __restrict__ gW2,
    float* sW, int tid, float acc1[4][4], float acc2[4][4]) {

    const int lane = tid & 31, warp = tid >> 5;
    const int gid = lane >> 2, ctg = lane & 3;
    const int r0 = (warp & 1) * 16;
    const int c0 = (warp >> 1) * 32;

    #pragma unroll
    for (int nt = 0; nt < 4; nt++)
        #pragma unroll
        for (int j = 0; j < 4; j++) { acc1[nt][j] = 0.f; acc2[nt][j] = 0.f; }

    for (int kc = 0; kc < CDIM; kc += 64) {
        __syncthreads();   // protect sW from previous chunk's readers
        #pragma unroll
        for (int i = 0; i < 8; i++) {
            int e = tid + i * 256;
            int r = e >> 5, c4 = e & 31;
            cp16(sW + r * SW_STRIDE + c4 * 4, gW1 + (size_t)(kc + r) * CDIM + c4 * 4);
            cp16(sW + 64 * SW_STRIDE + r * SW_STRIDE + c4 * 4,
                 gW2 + (size_t)(kc + r) * CDIM + c4 * 4);
        }
        asm volatile("cp.async.commit_group;\ncp.async.wait_group 0;" ::: "memory");
        __syncthreads();

        #pragma unroll
        for (int ks = 0; ks < 8; ks++) {
            int kg = kc + ks * 8;
            uint32_t a1h[4], a1l[4], a2h[4], a2l[4];
            {
                const float* ap = sA1 + (r0 + gid) * SA_STRIDE + kg + ctg;
                float x;
                x = ap[0];               a1h[0] = f2tf32(x); a1l[0] = f2tf32(x - __uint_as_float(a1h[0]));
                x = ap[8 * SA_STRIDE];   a1h[1] = f2tf32(x); a1l[1] = f2tf32(x - __uint_as_float(a1h[1]));
                x = ap[4];               a1h[2] = f2tf32(x); a1l[2] = f2tf32(x - __uint_as_float(a1h[2]));
                x = ap[8 * SA_STRIDE+4]; a1h[3] = f2tf32(x); a1l[3] = f2tf32(x - __uint_as_float(a1h[3]));
            }
            if (!SAME_A) {
                const float* ap = sA2 + (r0 + gid) * SA_STRIDE + kg + ctg;
                float x;
                x = ap[0];               a2h[0] = f2tf32(x); a2l[0] = f2tf32(x - __uint_as_float(a2h[0]));
                x = ap[8 * SA_STRIDE];   a2h[1] = f2tf32(x); a2l[1] = f2tf32(x - __uint_as_float(a2h[1]));
                x = ap[4];               a2h[2] = f2tf32(x); a2l[2] = f2tf32(x - __uint_as_float(a2h[2]));
                x = ap[8 * SA_STRIDE+4]; a2h[3] = f2tf32(x); a2l[3] = f2tf32(x - __uint_as_float(a2h[3]));
            }
            #pragma unroll
            for (int nt = 0; nt < 4; nt++) {
                const float* bp = sW + (ks * 8 + ctg) * SW_STRIDE + c0 + nt * 8 + gid;
                uint32_t bh[2], bl[2];
                float b0 = bp[0], b1 = bp[4 * SW_STRIDE];
                bh[0] = f2tf32(b0); bl[0] = f2tf32(b0 - __uint_as_float(bh[0]));
                bh[1] = f2tf32(b1); bl[1] = f2tf32(b1 - __uint_as_float(bh[1]));
                mma_tf32(acc1[nt], a1h, bh);
                mma_tf32(acc1[nt], a1h, bl);
                mma_tf32(acc1[nt], a1l, bh);
                const float* bp2 = bp + 64 * SW_STRIDE;
                b0 = bp2[0]; b1 = bp2[4 * SW_STRIDE];
                bh[0] = f2tf32(b0); bl[0] = f2tf32(b0 - __uint_as_float(bh[0]));
                bh[1] = f2tf32(b1); bl[1] = f2tf32(b1 - __uint_as_float(bh[1]));
                if (SAME_A) {
                    mma_tf32(acc2[nt], a1h, bh);
                    mma_tf32(acc2[nt], a1h, bl);
                    mma_tf32(acc2[nt], a1l, bh);
                } else {
                    mma_tf32(acc2[nt], a2h, bh);
                    mma_tf32(acc2[nt], a2h, bl);
                    mma_tf32(acc2[nt], a2l, bh);
                }
            }
        }
    }
}

#define SMEM_SIDE_FLOATS (2 * 32 * SA_STRIDE + 2 * 64 * SW_STRIDE)
#define SMEM_SIDE_BYTES  (SMEM_SIDE_FLOATS * 4)

// ------------------------------ side kernel --------------------------------
template<int SIDE>
__global__ __launch_bounds__(256) void side_kernel(
    const float* __restrict__ ga, const float* __restrict__ gs,
    const float* __restrict__ sscale,
    const float* __restrict__ Wg, const float* __restrict__ bg,
    const float* __restrict__ Wb,
    const float* __restrict__ W1, const float* __restrict__ b1,
    const float* __restrict__ W2,
    float* __restrict__ out1, float* __restrict__ out2) {

    extern __shared__ float smem[];
    float* sA = smem;
    float* sS = smem + 32 * SA_STRIDE;
    float* sW = smem + 2 * 32 * SA_STRIDE;

    const int tid = threadIdx.x;
    const int lane = tid & 31, warp = tid >> 5;
    const int gid = lane >> 2, ctg = lane & 3;
    const int r0 = (warp & 1) * 16;
    const int c0 = (warp >> 1) * 32;
    const int row0 = blockIdx.x * 32;

    {
        float4 sc = ((const float4*)sscale)[lane];
        #pragma unroll
        for (int rr = 0; rr < 4; rr++) {
            int lrow = rr * 8 + warp;
            const float4* ap = (const float4*)(ga + (size_t)(row0 + lrow) * CDIM);
            const float4* sp = (const float4*)(gs + (size_t)(row0 + lrow) * CDIM);
            float4 av = ap[lane];
            float4 sv = sp[lane];
            float s1 = av.x + av.y + av.z + av.w;
            float s2 = av.x*av.x + av.y*av.y + av.z*av.z + av.w*av.w;
            float t1 = sv.x + sv.y + sv.z + sv.w;
            float t2 = sv.x*sv.x + sv.y*sv.y + sv.z*sv.z + sv.w*sv.w;
            #pragma unroll
            for (int o = 16; o > 0; o >>= 1) {
                s1 += __shfl_xor_sync(~0u, s1, o);
                s2 += __shfl_xor_sync(~0u, s2, o);
                t1 += __shfl_xor_sync(~0u, t1, o);
                t2 += __shfl_xor_sync(~0u, t2, o);
            }
            float ma = s1 * (1.f/CDIM);
            float ra = rsqrtf(s2 * (1.f/CDIM) - ma*ma + EPS);
            float ms = t1 * (1.f/CDIM);
            float rs = rsqrtf(t2 * (1.f/CDIM) - ms*ms + EPS);
            float* pa = sA + lrow * SA_STRIDE + lane * 4;
            float* ps = sS + lrow * SA_STRIDE + lane * 4;
            pa[0] = (av.x - ma) * ra; pa[1] = (av.y - ma) * ra;
            pa[2] = (av.z - ma) * ra; pa[3] = (av.w - ma) * ra;
            ps[0] = (sv.x - ms) * rs * sc.x; ps[1] = (sv.y - ms) * rs * sc.y;
            ps[2] = (sv.z - ms) * rs * sc.z; ps[3] = (sv.w - ms) * rs * sc.w;
        }
    }
    __syncthreads();

    float accG[4][4], accB[4][4];
    gemm_dual<true>(sS, sS, Wg, Wb, sW, tid, accG, accB);

    __syncthreads();
    #pragma unroll
    for (int nt = 0; nt < 4; nt++) {
        int col = c0 + nt * 8 + 2 * ctg;
        float bg0 = bg[col], bg1 = bg[col + 1];
        #pragma unroll
        for (int i = 0; i < 2; i++) {
            int lrow = r0 + gid + i * 8;
            float* pr = sS + lrow * SA_STRIDE + col;
            const float* pl = sA + lrow * SA_STRIDE + col;
            pr[0] = sigmoidf_(accG[nt][2*i]   + bg0) * pl[0] + accB[nt][2*i];
            pr[1] = sigmoidf_(accG[nt][2*i+1] + bg1) * pl[1] + accB[nt][2*i+1];
        }
    }

    float acc1[4][4], acc2[4][4];
    gemm_dual<true>(sS, sS, W1, W2, sW, tid, acc1, acc2);

    #pragma unroll
    for (int nt = 0; nt < 4; nt++) {
        int col = c0 + nt * 8 + 2 * ctg;
        float bb0 = 0.f, bb1 = 0.f;
        if (SIDE == 0) { bb0 = b1[col]; bb1 = b1[col + 1]; }
        #pragma unroll
        for (int i = 0; i < 2; i++) {
            int grow = row0 + r0 + gid + i * 8;
            size_t idx = (size_t)grow * CDIM + col;
            if (SIDE == 0) {
                out1[idx]     = (acc1[nt][2*i]   + bb0) * QK_SCALE;
                out1[idx + 1] = (acc1[nt][2*i+1] + bb1) * QK_SCALE;
                out2[idx]     = sigmoidf_(acc2[nt][2*i]);
                out2[idx + 1] = sigmoidf_(acc2[nt][2*i+1]);
            } else {
                out1[idx]     = acc1[nt][2*i];
                out1[idx + 1] = acc1[nt][2*i+1];
                out2[idx]     = acc2[nt][2*i];
                out2[idx + 1] = acc2[nt][2*i+1];
            }
        }
    }
}

// ------------------------------ final kernel -------------------------------
__global__ __launch_bounds__(256) void final_kernel(
    const float* __restrict__ og, const float* __restrict__ sq,
    const float* __restrict__ Wo, const float* __restrict__ Ws,
    const float* __restrict__ bs, float* __restrict__ out) {

    extern __shared__ float smem[];
    float* sA1 = smem;
    float* sA2 = smem + 32 * SA_STRIDE;
    float* sW  = smem + 2 * 32 * SA_STRIDE;

    const int tid = threadIdx.x;
    const int lane = tid & 31, warp = tid >> 5;
    const int gid = lane >> 2, ctg = lane & 3;
    const int r0 = (warp & 1) * 16;
    const int c0 = (warp >> 1) * 32;
    const int row0 = blockIdx.x * 32;

    #pragma unroll
    for (int i = 0; i < 4; i++) {
        int e = tid + i * 256;
        int r = e >> 5, c4 = e & 31;
        cp16(sA1 + r * SA_STRIDE + c4 * 4, og + (size_t)(row0 + r) * CDIM + c4 * 4);
        cp16(sA2 + r * SA_STRIDE + c4 * 4, sq + (size_t)(row0 + r) * CDIM + c4 * 4);
    }
    asm volatile("cp.async.commit_group;\ncp.async.wait_group 0;" ::: "memory");

    float acc1[4][4], acc2[4][4];
    gemm_dual<false>(sA1, sA2, Wo, Ws, sW, tid, acc1, acc2);

    #pragma unroll
    for (int nt = 0; nt < 4; nt++) {
        int col = c0 + nt * 8 + 2 * ctg;
        float b0 = bs[col], b1 = bs[col + 1];
        #pragma unroll
        for (int i = 0; i < 2; i++) {
            int grow = row0 + r0 + gid + i * 8;
            size_t idx = (size_t)grow * CDIM + col;
            out[idx]     = sigmoidf_(acc2[nt][2*i]   + b0) * acc1[nt][2*i];
            out[idx + 1] = sigmoidf_(acc2[nt][2*i+1] + b1) * acc1[nt][2*i+1];
        }
    }
}

// --------------------------- attention kernel ------------------------------
// 384 threads: warps 0-7 consumers (flash attention), warps 8-11 producers
// (z-bias for next tile into double-buffered Psm).
// Named barriers: 1,2 = full[0,1] (count 384); 3,4 = empty[0,1] (count 384);
//                 5 = consumer-only K/V reuse guard (count 256).
#define K_STRIDE 132
#define V_STRIDE 136
#define P_STRIDE 68
#define PBUF (NHEAD * 32 * P_STRIDE)
#define SMEM_FLOATS (64 * K_STRIDE + 64 * V_STRIDE + 2 * PBUF)
#define SMEM_BYTES  (SMEM_FLOATS * 4)
#define NTILES (NSEQ / 64)

__global__ __launch_bounds__(384, 1) void attn_kernel(
    const float* __restrict__ z,
    const float* __restrict__ gq, const float* __restrict__ gk,
    const float* __restrict__ gv, const float* __restrict__ gg,
    float* __restrict__ og) {

    extern __shared__ float smem[];
    float* Ksm = smem;
    float* Vsm = smem + 64 * K_STRIDE;
    float* Psm = Vsm + 64 * V_STRIDE;

    const int tid = threadIdx.x;
    const int qg0 = blockIdx.x * 32;

    if (tid >= 256) {
        // ======================= PRODUCER warps =======================
        const int ptid = tid - 256;
        const int kk0 = ptid & 63;           // key column within tile
        const int qq0 = ptid >> 6;           // 0 or 1; q = qq0 + 2*qi
        const float csum0 = c_bias[64], csum1 = c_bias[65];
        const float csum2 = c_bias[66], csum3 = c_bias[67];

        // 2-deep rolling z prefetch across the whole tile sequence
        float4 zb[2][4];
        #pragma unroll
        for (int u = 0; u < 2; u++) {
            const float4* zp = (const float4*)(z + ((size_t)(qg0 + qq0 + u * 2) * NSEQ + kk0) * CZ);
            zb[u][0] = zp[0]; zb[u][1] = zp[1]; zb[u][2] = zp[2]; zb[u][3] = zp[3];
        }

        for (int t = 0; t < NTILES; t++) {
            float* Pbuf = Psm + (t & 1) * PBUF;
            if (t >= 2)
                asm volatile("bar.sync %0, 384;" :: "r"(3 + (t & 1)) : "memory");
            const int kb = t * 64;
            #pragma unroll 4
            for (int qi = 0; qi < 16; qi++) {
                const int pb2 = qi & 1;      // t*16 even -> (u&1) == (qi&1)
                float4 zc[4] = { zb[pb2][0], zb[pb2][1], zb[pb2][2], zb[pb2][3] };
                // prefetch u+2
                {
                    int qin = (qi + 2) & 15;
                    int kbn = kb + (((qi + 2) >> 4) << 6);
                    if (kbn >= NSEQ) kbn = 0;   // tail: harmless valid reload
                    const float4* zn = (const float4*)(z + ((size_t)(qg0 + qq0 + qin * 2) * NSEQ + kbn + kk0) * CZ);
                    zb[pb2][0] = zn[0]; zb[pb2][1] = zn[1];
                    zb[pb2][2] = zn[2]; zb[pb2][3] = zn[3];
                }
                float s1 = 0.f, s2 = 0.f, d0 = 0.f, d1 = 0.f, d2 = 0.f, d3 = 0.f;
                #pragma unroll
                for (int j = 0; j < 4; j++) {
                    float4 v = zc[j];
                    int cb = j * 4;
                    s1 += v.x + v.y + v.z + v.w;
                    s2 += v.x*v.x + v.y*v.y + v.z*v.z + v.w*v.w;
                    d0 += v.x*c_bias[(cb+0)*4+0]; d1 += v.x*c_bias[(cb+0)*4+1];
                    d2 += v.x*c_bias[(cb+0)*4+2]; d3 += v.x*c_bias[(cb+0)*4+3];
                    d0 += v.y*c_bias[(cb+1)*4+0]; d1 += v.y*c_bias[(cb+1)*4+1];
                    d2 += v.y*c_bias[(cb+1)*4+2]; d3 += v.y*c_bias[(cb+1)*4+3];
                    d0 += v.z*c_bias[(cb+2)*4+0]; d1 += v.z*c_bias[(cb+2)*4+1];
                    d2 += v.z*c_bias[(cb+2)*4+2]; d3 += v.z*c_bias[(cb+2)*4+3];
                    d0 += v.w*c_bias[(cb+3)*4+0]; d1 += v.w*c_bias[(cb+3)*4+1];
                    d2 += v.w*c_bias[(cb+3)*4+2]; d3 += v.w*c_bias[(cb+3)*4+3];
                }
                float mm = s1 * (1.f/CZ);
                float rstd = rsqrtf(s2 * (1.f/CZ) - mm * mm + EPS);
                int q = qq0 + qi * 2;
                float* pb = Pbuf + q * P_STRIDE + kk0;
                pb[0 * 32 * P_STRIDE] = (d0 - mm * csum0) * rstd;
                pb[1 * 32 * P_STRIDE] = (d1 - mm * csum1) * rstd;
                pb[2 * 32 * P_STRIDE] = (d2 - mm * csum2) * rstd;
                pb[3 * 32 * P_STRIDE] = (d3 - mm * csum3) * rstd;
            }
            asm volatile("bar.arrive %0, 384;" :: "r"(1 + (t & 1)) : "memory");
        }
        return;
    }

    // ======================= CONSUMER warps =======================
    const int lane = tid & 31, warp = tid >> 5;
    const int h = warp >> 1, qh = warp & 1;
    const int gid = lane >> 2, ctg = lane & 3;

    // Q fragments (A of m16n8k8 tf32), q pre-scaled by 1/sqrt(c)
    uint32_t qa[4][4];
    {
        int r0 = qg0 + qh * 16 + gid;
        const float* qp = gq + (size_t)r0 * CDIM + h * HDIM + ctg;
        #pragma unroll
        for (int ks = 0; ks < 4; ks++) {
            qa[ks][0] = f2tf32(qp[ks*8]);
            qa[ks][1] = f2tf32(qp[8*CDIM + ks*8]);
            qa[ks][2] = f2tf32(qp[ks*8 + 4]);
            qa[ks][3] = f2tf32(qp[8*CDIM + ks*8 + 4]);
        }
    }

    float O[4][4];
    #pragma unroll
    for (int i = 0; i < 4; i++) { O[i][0]=O[i][1]=O[i][2]=O[i][3]=0.f; }
    float m1 = -1e30f, m2 = -1e30f, l1 = 0.f, l2 = 0.f;

    for (int t = 0; t < NTILES; t++) {
        const int kb = t * 64;
        // all consumers done reading previous K/V tile
        asm volatile("bar.sync 5, 256;" ::: "memory");

        // prefetch K/V tile (256 consumer threads)
        #pragma unroll
        for (int i = 0; i < 8; i++) {
            int e = tid + i * 256;
            int r = e >> 5, c4 = e & 31;
            cp16(Ksm + r * K_STRIDE + c4 * 4, gk + (size_t)(kb + r) * CDIM + c4 * 4);
        }
        #pragma unroll
        for (int i = 0; i < 8; i++) {
            int e = tid + i * 256;
            int r = e >> 5, c4 = e & 31;
            cp16(Vsm + r * V_STRIDE + c4 * 4, gv + (size_t)(kb + r) * CDIM + c4 * 4);
        }
        asm volatile("cp.async.commit_group;\ncp.async.wait_group 0;" ::: "memory");

        // wait for producers' bias tile (also rendezvous: everyone's cp.async done)
        asm volatile("bar.sync %0, 384;" :: "r"(1 + (t & 1)) : "memory");
        float* Pbuf = Psm + (t & 1) * PBUF;

        // ---- QK^T (tf32 mma): S[16q x 64k] per warp
        float S[8][4];
        #pragma unroll
        for (int nt = 0; nt < 8; nt++) {
            S[nt][0] = S[nt][1] = S[nt][2] = S[nt][3] = 0.f;
            const float* kp = Ksm + (nt * 8 + gid) * K_STRIDE + h * HDIM + ctg;
            #pragma unroll
            for (int ks = 0; ks < 4; ks++) {
                uint32_t b[2];
                b[0] = __float_as_uint(kp[ks * 8]);
                b[1] = __float_as_uint(kp[ks * 8 + 4]);
                mma_tf32(S[nt], qa[ks], b);
            }
        }

        // ---- bias add + online softmax
        float* pwarp = Pbuf + h * 32 * P_STRIDE + (qh * 16) * P_STRIDE;
        float mx1 = -1e30f, mx2 = -1e30f;
        #pragma unroll
        for (int nt = 0; nt < 8; nt++) {
            int col = nt * 8 + 2 * ctg;
            S[nt][0] += pwarp[gid * P_STRIDE + col];
            S[nt][1] += pwarp[gid * P_STRIDE + col + 1];
            S[nt][2] += pwarp[(gid + 8) * P_STRIDE + col];
            S[nt][3] += pwarp[(gid + 8) * P_STRIDE + col + 1];
            mx1 = fmaxf(mx1, fmaxf(S[nt][0], S[nt][1]));
            mx2 = fmaxf(mx2, fmaxf(S[nt][2], S[nt][3]));
        }
        mx1 = fmaxf(mx1, __shfl_xor_sync(~0u, mx1, 1));
        mx1 = fmaxf(mx1, __shfl_xor_sync(~0u, mx1, 2));
        mx2 = fmaxf(mx2, __shfl_xor_sync(~0u, mx2, 1));
        mx2 = fmaxf(mx2, __shfl_xor_sync(~0u, mx2, 2));
        float mn1 = fmaxf(m1, mx1), mn2 = fmaxf(m2, mx2);
        float al1 = __expf(m1 - mn1), al2 = __expf(m2 - mn2);
        float rs1 = 0.f, rs2 = 0.f;
        #pragma unroll
        for (int nt = 0; nt < 8; nt++) {
            float p0 = __expf(S[nt][0] - mn1);
            float p1 = __expf(S[nt][1] - mn1);
            float p2 = __expf(S[nt][2] - mn2);
            float p3 = __expf(S[nt][3] - mn2);
            rs1 += p0 + p1; rs2 += p2 + p3;
            int col = nt * 8 + 2 * ctg;
            pwarp[gid * P_STRIDE + col]           = __uint_as_float(f2tf32(p0));
            pwarp[gid * P_STRIDE + col + 1]       = __uint_as_float(f2tf32(p1));
            pwarp[(gid + 8) * P_STRIDE + col]     = __uint_as_float(f2tf32(p2));
            pwarp[(gid + 8) * P_STRIDE + col + 1] = __uint_as_float(f2tf32(p3));
        }
        rs1 += __shfl_xor_sync(~0u, rs1, 1); rs1 += __shfl_xor_sync(~0u, rs1, 2);
        rs2 += __shfl_xor_sync(~0u, rs2, 1); rs2 += __shfl_xor_sync(~0u, rs2, 2);
        l1 = l1 * al1 + rs1; l2 = l2 * al2 + rs2;
        m1 = mn1; m2 = mn2;
        #pragma unroll
        for (int on = 0; on < 4; on++) {
            O[on][0] *= al1; O[on][1] *= al1; O[on][2] *= al2; O[on][3] *= al2;
        }
        __syncwarp();

        // ---- PV (tf32 mma): O[16q x 32c] += P[16q x 64k] @ V[64k x 32c]
        #pragma unroll
        for (int on = 0; on < 4; on++) {
            #pragma unroll
            for (int ks = 0; ks < 8; ks++) {
                uint32_t a[4], b[2];
                const float* pp = pwarp + gid * P_STRIDE + ks * 8 + ctg;
                a[0] = __float_as_uint(pp[0]);
                a[1] = __float_as_uint(pp[8 * P_STRIDE]);
                a[2] = __float_as_uint(pp[4]);
                a[3] = __float_as_uint(pp[8 * P_STRIDE + 4]);
                const float* vp = Vsm + (ks * 8 + ctg) * V_STRIDE + h * HDIM + on * 8 + gid;
                b[0] = __float_as_uint(vp[0]);
                b[1] = __float_as_uint(vp[4 * V_STRIDE]);
                mma_tf32(O[on], a, b);
            }
        }
        // release Psm buffer to producers
        asm volatile("bar.arrive %0, 384;" :: "r"(3 + (t & 1)) : "memory");
    }

    // ---- epilogue: normalize, gate, store
    float r1 = 1.f / l1, r2 = 1.f / l2;
    int row1 = qg0 + qh * 16 + gid, row2 = row1 + 8;
    #pragma unroll
    for (int on = 0; on < 4; on++) {
        int col = h * HDIM + on * 8 + 2 * ctg;
        size_t i1 = (size_t)row1 * CDIM + col;
        size_t i2 = (size_t)row2 * CDIM + col;
        og[i1]     = O[on][0] * r1 * gg[i1];
        og[i1 + 1] = O[on][1] * r1 * gg[i1 + 1];
        og[i2]     = O[on][2] * r2 * gg[i2];
        og[i2 + 1] = O[on][3] * r2 * gg[i2 + 1];
    }
}

// ------------------------------ launch -------------------------------------
extern "C" void kernel_launch(void* const* d_in, const int* in_sizes, int n_in,
                              void* d_out, int out_size) {
    const float* a_q      = (const float*)d_in[0];
    const float* a_k      = (const float*)d_in[1];
    const float* z        = (const float*)d_in[2];
    const float* s_q      = (const float*)d_in[3];
    const float* s_k      = (const float*)d_in[4];
    const float* Wg_q     = (const float*)d_in[5];
    const float* bg_q     = (const float*)d_in[6];
    const float* Wb_q     = (const float*)d_in[7];
    const float* sscale_q = (const float*)d_in[8];
    const float* Wg_k     = (const float*)d_in[9];
    const float* bg_k     = (const float*)d_in[10];
    const float* Wb_k     = (const float*)d_in[11];
    const float* sscale_k = (const float*)d_in[12];
    const float* lnz      = (const float*)d_in[13];
    const float* Wq       = (const float*)d_in[14];
    const float* bq       = (const float*)d_in[15];
    const float* Wk       = (const float*)d_in[16];
    const float* Wv       = (const float*)d_in[17];
    const float* Wbias    = (const float*)d_in[18];
    const float* Wgate    = (const float*)d_in[19];
    const float* Wo       = (const float*)d_in[20];
    const float* Ws       = (const float*)d_in[21];
    const float* bs       = (const float*)d_in[22];

    float* scratch = nullptr;
    cudaGetSymbolAddress((void**)&scratch, g_scratch);
    const size_t SL = (size_t)NSEQ * CDIM;
    float* qbuf  = scratch + 0 * SL;
    float* gbuf  = scratch + 1 * SL;
    float* kbuf  = scratch + 2 * SL;
    float* vbuf  = scratch + 3 * SL;
    float* ogbuf = scratch + 4 * SL;
    float* biasw = scratch + 5 * SL;

    init_bias<<<1, 96>>>(lnz, Wbias, biasw);
    cudaMemcpyToSymbolAsync(c_bias, biasw, (CZ * NHEAD + NHEAD) * sizeof(float), 0,
                            cudaMemcpyDeviceToDevice, 0);

    cudaFuncSetAttribute(side_kernel<0>, cudaFuncAttributeMaxDynamicSharedMemorySize,
                         SMEM_SIDE_BYTES);
    cudaFuncSetAttribute(side_kernel<1>, cudaFuncAttributeMaxDynamicSharedMemorySize,
                         SMEM_SIDE_BYTES);
    cudaFuncSetAttribute(final_kernel, cudaFuncAttributeMaxDynamicSharedMemorySize,
                         SMEM_SIDE_BYTES);
    cudaFuncSetAttribute(attn_kernel, cudaFuncAttributeMaxDynamicSharedMemorySize,
                         SMEM_BYTES);

    side_kernel<0><<<NSEQ / 32, 256, SMEM_SIDE_BYTES>>>(
        a_q, s_q, sscale_q, Wg_q, bg_q, Wb_q, Wq, bq, Wgate, qbuf, gbuf);
    side_kernel<1><<<NSEQ / 32, 256, SMEM_SIDE_BYTES>>>(
        a_k, s_k, sscale_k, Wg_k, bg_k, Wb_k, Wk, nullptr, Wv, kbuf, vbuf);

    attn_kernel<<<NSEQ / 32, 384, SMEM_BYTES>>>(z, qbuf, kbuf, vbuf, gbuf, ogbuf);

    final_kernel<<<NSEQ / 32, 256, SMEM_SIDE_BYTES>>>(
        ogbuf, s_q, Wo, Ws, bs, (float*)d_out);
}